// round 1
// baseline (speedup 1.0000x reference)
#include <cuda_runtime.h>
#include <math_constants.h>

// Problem geometry (fixed by the reference):
//   queries/keys/values: [1, 32, 8, 32] fp32 -> 8192 floats each
//   segment length Ls=4 -> 8 segments of 4*8*32 = 1024 contiguous floats
//   dists[i][j] = exact DTW(|a-b| cost) between q-seg i and k-seg j (1024 x 1024 DP)
//   A = softmax(0.5 * dists, axis=-1)   (8x8)
//   out[i*1024 + r] = sum_j A[i][j] * values[j*1024 + r]

#define N_SEG    8
#define SEG_LEN  1024          // B*Ls*H*D
#define N_ROWS   SEG_LEN
#define T_COLS   8             // columns per thread
#define P_THR    128           // threads per CTA (P_THR * T_COLS == SEG_LEN)
#define N_STEPS  (N_ROWS + P_THR - 1)   // 1151 pipeline steps

__device__ float g_dists[N_SEG * N_SEG];

// One CTA per (query segment, key segment) pair. Pipelined column-tile DTW:
// thread t owns columns [8t, 8t+8); at step s it processes row r = s - t.
// Only the tile's right-boundary d value crosses threads, via 3 rotating
// smem buffers (write buffer never aliases either read buffer within a step,
// so a single __syncthreads per step suffices).
__global__ __launch_bounds__(P_THR, 1)
void dtw_kernel(const float* __restrict__ q, const float* __restrict__ k) {
    const int qi = blockIdx.x;
    const int kj = blockIdx.y;
    const float* __restrict__ xrow = q + qi * SEG_LEN;   // DP rows
    const float* __restrict__ ycol = k + kj * SEG_LEN;   // DP cols

    __shared__ float sx[N_ROWS];
    __shared__ float buf0[P_THR];
    __shared__ float buf1[P_THR];
    __shared__ float buf2[P_THR];

    const int t = threadIdx.x;

    // Stage the row sequence into smem once.
    for (int i = t; i < N_ROWS; i += P_THR) sx[i] = xrow[i];

    const int base = t * T_COLS;
    float y[T_COLS];
    float prev[T_COLS];               // d[r-1, base..base+7]
    const float INF = CUDART_INF_F;
#pragma unroll
    for (int j = 0; j < T_COLS; j++) {
        y[j]    = ycol[base + j];
        prev[j] = INF;                // virtual row -1 = +inf
    }
    __syncthreads();

    // Rotating buffer pointers: pw = step s, pl = step s-1, pd = step s-2.
    float* pw = buf0;
    float* pl = buf2;
    float* pd = buf1;

    for (int s = 0; s < N_STEPS; s++) {
        const int r = s - t;
        if (0 <= r && r < N_ROWS) {
            float left, dpr;
            if (t == 0) {
                left = INF;                        // d[r, -1]
                dpr  = (r == 0) ? 0.0f : INF;      // d[r-1, -1]; d[-1,-1]=0
            } else {
                left = pl[t - 1];                  // d[r,   base-1] (neighbor, step s-1)
                dpr  = (r == 0) ? INF : pd[t - 1]; // d[r-1, base-1] (neighbor, step s-2)
            }
            const float xr = sx[r];
            float d;
#pragma unroll
            for (int j = 0; j < T_COLS; j++) {
                const float c = fabsf(xr - y[j]);
                const float a = fminf(prev[j], dpr);   // min(d[r-1,j], d[r-1,j-1])
                d = c + fminf(a, left);
                dpr     = prev[j];
                prev[j] = d;
                left    = d;
            }
            pw[t] = d;   // boundary value for the right neighbor
        }
        __syncthreads();
        // rotate: step s+1 writes into the (s-2) buffer
        float* tmp = pd;
        pd = pl;
        pl = pw;
        pw = tmp;
    }

    if (t == P_THR - 1) {
        g_dists[qi * N_SEG + kj] = prev[T_COLS - 1];   // d[1023, 1023]
    }
}

// One CTA per query segment: 8-wide softmax then weighted sum of value segments.
__global__ __launch_bounds__(SEG_LEN)
void attend_kernel(const float* __restrict__ values, float* __restrict__ out) {
    const int i = blockIdx.x;
    __shared__ float w[N_SEG];

    if (threadIdx.x == 0) {
        float l[N_SEG];
        float m = -CUDART_INF_F;
#pragma unroll
        for (int j = 0; j < N_SEG; j++) {
            l[j] = 0.5f * g_dists[i * N_SEG + j];   // scale = 1/sqrt(4)
            m = fmaxf(m, l[j]);
        }
        float ssum = 0.0f;
#pragma unroll
        for (int j = 0; j < N_SEG; j++) {
            const float e = expf(l[j] - m);
            w[j] = e;
            ssum += e;
        }
        const float inv = 1.0f / ssum;
#pragma unroll
        for (int j = 0; j < N_SEG; j++) w[j] *= inv;
    }
    __syncthreads();

    const int r = threadIdx.x;      // 0..1023 within the segment
    float acc = 0.0f;
#pragma unroll
    for (int j = 0; j < N_SEG; j++) {
        acc += w[j] * values[j * SEG_LEN + r];
    }
    out[i * SEG_LEN + r] = acc;
}

extern "C" void kernel_launch(void* const* d_in, const int* in_sizes, int n_in,
                              void* d_out, int out_size) {
    const float* queries = (const float*)d_in[0];
    const float* keys    = (const float*)d_in[1];
    const float* values  = (const float*)d_in[2];
    // d_in[3] (attn_mask) is unused, as in the reference.
    float* out = (float*)d_out;

    dim3 grid(N_SEG, N_SEG);
    dtw_kernel<<<grid, P_THR>>>(queries, keys);
    attend_kernel<<<N_SEG, SEG_LEN>>>(values, out);
}

// round 2
// speedup vs baseline: 2.0695x; 2.0695x over previous
#include <cuda_runtime.h>
#include <math_constants.h>

// Problem geometry (fixed by the reference):
//   queries/keys/values: [1, 32, 8, 32] fp32 -> 8192 floats each
//   segment length Ls=4 -> 8 segments of 4*8*32 = 1024 contiguous floats
//   dists[i][j] = exact DTW(|a-b| cost) between q-seg i and k-seg j (1024x1024 DP)
//   A = softmax(0.5 * dists, axis=-1)   (8x8)
//   out[i*1024 + r] = sum_j A[i][j] * values[j*1024 + r]

#define N_SEG    8
#define SEG_LEN  1024
#define N_ROWS   SEG_LEN
#define C_COLS   8                       // columns per thread
#define R_ROWS   8                       // rows per pipeline step
#define P_THR    128                     // threads per CTA (P_THR*C_COLS == SEG_LEN)
#define N_BLK    (N_ROWS / R_ROWS)       // 128 row-blocks
#define N_STEPS  (N_BLK + P_THR - 1)     // 255 pipeline steps

__device__ float g_dists[N_SEG * N_SEG];

// One CTA per (query segment, key segment) pair.
// Pipelined 8x8 register-tile DTW: thread t owns columns [8t, 8t+8); at step s
// it processes rows [8(s-t), 8(s-t)+8). Only the 8 right-boundary d values of
// the tile cross threads, batched as two float4s in a double-buffered smem
// array (one __syncthreads per step). d[r0-1, base-1] is carried in a register
// from the previous step's batch.
__global__ __launch_bounds__(P_THR, 1)
void dtw_kernel(const float* __restrict__ q, const float* __restrict__ k) {
    const int qi = blockIdx.x;
    const int kj = blockIdx.y;
    const float* __restrict__ xrow = q + qi * SEG_LEN;   // DP rows
    const float* __restrict__ ycol = k + kj * SEG_LEN;   // DP cols

    __shared__ float  sx[N_ROWS];
    __shared__ float4 bufA[P_THR][2];
    __shared__ float4 bufB[P_THR][2];

    const int t = threadIdx.x;
    const float INF = CUDART_INF_F;

    for (int i = t; i < N_ROWS; i += P_THR) sx[i] = xrow[i];

    const int base = t * C_COLS;
    float y[C_COLS];
    {
        const float4* y4 = reinterpret_cast<const float4*>(ycol + base);
        float4 a = y4[0], b = y4[1];
        y[0]=a.x; y[1]=a.y; y[2]=a.z; y[3]=a.w;
        y[4]=b.x; y[5]=b.y; y[6]=b.z; y[7]=b.w;
    }

    float prev[C_COLS];                  // d[r-1, base..base+7]
#pragma unroll
    for (int j = 0; j < C_COLS; j++) prev[j] = INF;

    // carry = d[r0-1, base-1] entering each step's first row.
    // t==0: first row ever is r=0, needing d[-1,-1]=0; afterwards INF.
    float carry = (t == 0) ? 0.0f : INF;

    __syncthreads();

    float4 (*wr)[2] = bufA;              // write buffer this step
    float4 (*rd)[2] = bufB;              // read buffer (neighbor, step s-1)

    for (int s = 0; s < N_STEPS; s++) {
        const int blk = s - t;
        if (0 <= blk && blk < N_BLK) {
            const int r0 = blk * R_ROWS;

            // Neighbor boundary values for rows r0..r0+7 (left column d's).
            float lv[R_ROWS];
            if (t == 0) {
#pragma unroll
                for (int rr = 0; rr < R_ROWS; rr++) lv[rr] = INF;
            } else {
                float4 a = rd[t - 1][0];
                float4 b = rd[t - 1][1];
                lv[0]=a.x; lv[1]=a.y; lv[2]=a.z; lv[3]=a.w;
                lv[4]=b.x; lv[5]=b.y; lv[6]=b.z; lv[7]=b.w;
            }

            // x values for this row block.
            float xr[R_ROWS];
            {
                const float4* x4 = reinterpret_cast<const float4*>(sx + r0);
                float4 a = x4[0], b = x4[1];
                xr[0]=a.x; xr[1]=a.y; xr[2]=a.z; xr[3]=a.w;
                xr[4]=b.x; xr[5]=b.y; xr[6]=b.z; xr[7]=b.w;
            }

            float out[R_ROWS];
#pragma unroll
            for (int rr = 0; rr < R_ROWS; rr++) {
                float left = lv[rr];
                float dpr  = (rr == 0) ? carry : lv[rr - 1];
                const float x = xr[rr];
#pragma unroll
                for (int j = 0; j < C_COLS; j++) {
                    const float c = fabsf(x - y[j]);
                    const float a = fminf(prev[j], dpr);   // min(up, up-left)
                    const float d = c + fminf(a, left);
                    dpr     = prev[j];
                    prev[j] = d;
                    left    = d;
                }
                out[rr] = left;                            // d[r, base+7]
            }
            carry = lv[R_ROWS - 1];

            wr[t][0] = make_float4(out[0], out[1], out[2], out[3]);
            wr[t][1] = make_float4(out[4], out[5], out[6], out[7]);
        }
        __syncthreads();
        float4 (*tmp)[2] = wr; wr = rd; rd = tmp;
    }

    if (t == P_THR - 1) {
        g_dists[qi * N_SEG + kj] = prev[C_COLS - 1];       // d[1023,1023]
    }
}

// One CTA per query segment; each thread redundantly computes the 8-wide
// softmax (no smem, no sync) and writes 4 outputs via float4.
__global__ __launch_bounds__(256)
void attend_kernel(const float* __restrict__ values, float* __restrict__ out) {
    const int i = blockIdx.x;

    float l[N_SEG];
    float m = -CUDART_INF_F;
#pragma unroll
    for (int j = 0; j < N_SEG; j++) {
        l[j] = 0.5f * g_dists[i * N_SEG + j];   // scale = 1/sqrt(4)
        m = fmaxf(m, l[j]);
    }
    float w[N_SEG];
    float ssum = 0.0f;
#pragma unroll
    for (int j = 0; j < N_SEG; j++) {
        w[j] = expf(l[j] - m);
        ssum += w[j];
    }
    const float inv = 1.0f / ssum;

    const float4* v4 = reinterpret_cast<const float4*>(values);
    const int tid = threadIdx.x;                // 0..255 -> float4 group
    float4 acc = make_float4(0.f, 0.f, 0.f, 0.f);
#pragma unroll
    for (int j = 0; j < N_SEG; j++) {
        const float wj = w[j] * inv;
        const float4 v = v4[j * (SEG_LEN / 4) + tid];
        acc.x += wj * v.x;
        acc.y += wj * v.y;
        acc.z += wj * v.z;
        acc.w += wj * v.w;
    }
    reinterpret_cast<float4*>(out)[i * (SEG_LEN / 4) + tid] = acc;
}

extern "C" void kernel_launch(void* const* d_in, const int* in_sizes, int n_in,
                              void* d_out, int out_size) {
    const float* queries = (const float*)d_in[0];
    const float* keys    = (const float*)d_in[1];
    const float* values  = (const float*)d_in[2];
    float* out = (float*)d_out;

    dim3 grid(N_SEG, N_SEG);
    dtw_kernel<<<grid, P_THR>>>(queries, keys);
    attend_kernel<<<N_SEG, 256>>>(values, out);
}